// round 13
// baseline (speedup 1.0000x reference)
#include <cuda_runtime.h>
#include <cuda_fp16.h>
#include <cstdint>

// Shapes (fixed for this problem)
#define B_ 4096
#define N_ 64
#define D_ 512
#define H_ 2
#define DK_ 256

// ---------------- scratch (static device arrays; no allocs) ----------------
__device__ __align__(16) __half g_src_h[(size_t)B_ * 512];
__device__ __align__(16) __half g_Wq_h[512 * 512];
__device__ __align__(16) __half g_Wk_h[512 * 512];
__device__ __align__(16) __half g_Wv_h[512 * 512];
__device__ __align__(16) __half g_WoT_h[512 * 512];          // Wo^T
__device__ __align__(16) __half g_W1T_h[512 * 1024];         // W1^T
__device__ __align__(16) __half g_W2T_h[512 * 512];          // W2^T
__device__ __align__(16) __half g_CkT[1024 * 512];           // CkT[c][i]
__device__ __align__(16) __half g_CvT[512 * 1024];           // CvT[j][c]
__device__ __align__(16) float  g_QT[(size_t)B_ * 1024];
__device__ __align__(16) __half g_CTX[(size_t)B_ * 1024];
__device__ __align__(16) float  g_PROJ[(size_t)B_ * 512];
__device__ __align__(16) __half g_LN[(size_t)B_ * 512];
__device__ __align__(16) __half g_H1[(size_t)B_ * 512];
__device__ int g_mask_word;   // 1 = 4-byte mask elements, 0 = 1-byte

// ---------------- helpers ----------------
__device__ __forceinline__ void cp16(void* s, const void* g)
{
    uint32_t sa = (uint32_t)__cvta_generic_to_shared(s);
    asm volatile("cp.async.cg.shared.global [%0], [%1], 16;" :: "r"(sa), "l"(g));
}
__device__ __forceinline__ void ldsm_x4(uint32_t& r0, uint32_t& r1,
                                        uint32_t& r2, uint32_t& r3, const void* p)
{
    uint32_t a = (uint32_t)__cvta_generic_to_shared(p);
    asm volatile("ldmatrix.sync.aligned.m8n8.x4.shared.b16 {%0,%1,%2,%3}, [%4];"
                 : "=r"(r0), "=r"(r1), "=r"(r2), "=r"(r3) : "r"(a));
}

// ---------------- mask dtype detection ----------------
__global__ void detect_mask_kernel(const unsigned int* __restrict__ m)
{
    __shared__ int bad;
    if (threadIdx.x == 0) bad = 0;
    __syncthreads();
    unsigned int w = m[threadIdx.x];
    if (!(w == 0u || w == 1u || w == 0x3F800000u)) atomicOr(&bad, 1);
    __syncthreads();
    if (threadIdx.x == 0) g_mask_word = bad ? 0 : 1;
}

// ---------------- pre-pass: fp16 copies + transposes ----------------
struct C16Entry { const float4* s; __half2* d; int n4; };
struct C16Batch { C16Entry e[4]; };
__global__ __launch_bounds__(256)
void cvt16_kernel(C16Batch p)
{
    const C16Entry& e = p.e[blockIdx.z];
    for (int i = blockIdx.x * 256 + threadIdx.x; i < e.n4; i += gridDim.x * 256) {
        float4 v = e.s[i];
        e.d[2 * i]     = __floats2half2_rn(v.x, v.y);
        e.d[2 * i + 1] = __floats2half2_rn(v.z, v.w);
    }
}

struct TrEntry { const float* s; __half* d; int rows, cols; };
struct TrBatch { TrEntry e[3]; };
__global__ __launch_bounds__(256)
void transpose_cvt_kernel(TrBatch p)
{
    const TrEntry& e = p.e[blockIdx.z];
    const int c0 = blockIdx.x * 32, r0 = blockIdx.y * 32;
    if (c0 >= e.cols || r0 >= e.rows) return;
    __shared__ float t[32][33];
    const int x = threadIdx.x & 31, y = threadIdx.x >> 5;  // 32 x 8
#pragma unroll
    for (int j = 0; j < 32; j += 8)
        t[y + j][x] = e.s[(size_t)(r0 + y + j) * e.cols + c0 + x];
    __syncthreads();
#pragma unroll
    for (int j = 0; j < 32; j += 8)
        e.d[(size_t)(c0 + y + j) * e.rows + r0 + x] = __float2half_rn(t[x][y + j]);
}

// ---------------- fp16 tensor-core GEMM (cp.async 3-stage, ldmatrix) --------
#define FLAG_BIAS  1
#define FLAG_RELU  2
#define FLAG_RESID 4
#define FLAG_OUT16 8

#define A_STRIDE_H 40                          // halves per SMEM row (32 used)
#define BBUF_H (128 * A_STRIDE_H)
#define GEMM_SMEM_MF(MF) (3 * ((MF) * 32 * A_STRIDE_H + BBUF_H) * 2)

template<int MF>   // CTA rows = MF*32
__device__ __forceinline__ void gemm_body(
    const __half* __restrict__ A, int lda,
    const __half* __restrict__ A2, int lda2, int ksplit,
    const __half* __restrict__ Bm, int ldb,
    void* __restrict__ C, int ldc,
    const float* __restrict__ bias,
    const float* __restrict__ resid, int ldr,
    int K, float alpha, int flags, int bm, int bn)
{
    constexpr int ABUF = MF * 32 * A_STRIDE_H;
    extern __shared__ __half smh[];
    __half* Asf = smh;                    // [3][MF*32 * A_STRIDE_H]
    __half* Bsf = smh + 3 * ABUF;         // [3][128 * A_STRIDE_H]

    const int tid = threadIdx.x;
    const int warp = tid >> 5, lane = tid & 31;
    const int wm = warp >> 2, wn = warp & 3;
    const int gid = lane >> 2, tig = lane & 3;

    const int a_row_l = (lane & 7) + ((lane >> 3) & 1) * 8;
    const int a_col_l = ((lane >> 4) & 1) * 8;
    const int b_row_l = ((lane >> 4) & 1) * 8 + (lane & 7);
    const int b_col_l = ((lane >> 3) & 1) * 8;

    float c[MF][4][4];
#pragma unroll
    for (int i = 0; i < MF; i++)
#pragma unroll
        for (int j = 0; j < 4; j++)
#pragma unroll
            for (int r = 0; r < 4; r++) c[i][j][r] = 0.f;

    const int KT = K >> 5;

    auto stage = [&](int kt, int slot) {
        const int k0 = kt * 32;
        __half* As = Asf + slot * ABUF;
        __half* Bs = Bsf + slot * BBUF_H;
#pragma unroll
        for (int j = 0; j < MF / 2; j++) {
            const int i = tid + 256 * j;
            const int row = i >> 2, c16 = i & 3;
            const int kg = k0 + c16 * 8;
            const __half* ap = (A2 != nullptr && kg >= ksplit)
                ? (A2 + (size_t)(bm + row) * lda2 + (kg - ksplit))
                : (A  + (size_t)(bm + row) * lda  + kg);
            cp16(As + row * A_STRIDE_H + c16 * 8, ap);
        }
#pragma unroll
        for (int j = 0; j < 2; j++) {
            const int i = tid + 256 * j;
            const int row = i >> 2, c16 = i & 3;
            cp16(Bs + row * A_STRIDE_H + c16 * 8,
                 Bm + (size_t)(bn + row) * ldb + k0 + c16 * 8);
        }
        asm volatile("cp.async.commit_group;" ::: "memory");
    };

    stage(0, 0);
    if (KT > 1) stage(1, 1);

    int slot = 0;
    for (int kt = 0; kt < KT; kt++) {
        asm volatile("cp.async.wait_group 1;" ::: "memory");
        __syncthreads();
        if (kt + 2 < KT) {
            int ns = slot + 2; if (ns >= 3) ns -= 3;
            stage(kt + 2, ns);
        }

        const __half* As = Asf + slot * ABUF;
        const __half* Bs = Bsf + slot * BBUF_H;
#pragma unroll
        for (int ks = 0; ks < 2; ks++) {
            uint32_t a[MF][4], b[4][2];
#pragma unroll
            for (int mf = 0; mf < MF; mf++) {
                const int r = wm * (MF * 16) + mf * 16 + a_row_l;
                ldsm_x4(a[mf][0], a[mf][1], a[mf][2], a[mf][3],
                        As + r * A_STRIDE_H + ks * 16 + a_col_l);
            }
#pragma unroll
            for (int nfp = 0; nfp < 2; nfp++) {
                const int cn = wn * 32 + nfp * 16 + b_row_l;
                ldsm_x4(b[2 * nfp][0], b[2 * nfp][1], b[2 * nfp + 1][0], b[2 * nfp + 1][1],
                        Bs + cn * A_STRIDE_H + ks * 16 + b_col_l);
            }
#pragma unroll
            for (int mf = 0; mf < MF; mf++)
#pragma unroll
                for (int nf = 0; nf < 4; nf++)
                    asm volatile(
                        "mma.sync.aligned.m16n8k16.row.col.f32.f16.f16.f32 "
                        "{%0,%1,%2,%3}, {%4,%5,%6,%7}, {%8,%9}, {%0,%1,%2,%3};"
                        : "+f"(c[mf][nf][0]), "+f"(c[mf][nf][1]),
                          "+f"(c[mf][nf][2]), "+f"(c[mf][nf][3])
                        : "r"(a[mf][0]), "r"(a[mf][1]), "r"(a[mf][2]), "r"(a[mf][3]),
                          "r"(b[nf][0]), "r"(b[nf][1]));
        }
        slot++; if (slot == 3) slot = 0;
    }

    // ---- epilogue ----
#pragma unroll
    for (int mf = 0; mf < MF; mf++) {
        const int r0 = bm + wm * (MF * 16) + mf * 16 + gid;
#pragma unroll
        for (int nf = 0; nf < 4; nf++) {
            const int cn = bn + wn * 32 + nf * 8 + tig * 2;
#pragma unroll
            for (int half = 0; half < 2; half++) {
                const int row = r0 + half * 8;
                float v0 = c[mf][nf][half * 2 + 0] * alpha;
                float v1 = c[mf][nf][half * 2 + 1] * alpha;
                if (flags & FLAG_BIAS)  { v0 += bias[cn]; v1 += bias[cn + 1]; }
                if (flags & FLAG_RESID) {
                    v0 += resid[(size_t)row * ldr + cn];
                    v1 += resid[(size_t)row * ldr + cn + 1];
                }
                if (flags & FLAG_RELU)  { v0 = fmaxf(v0, 0.f); v1 = fmaxf(v1, 0.f); }
                if (flags & FLAG_OUT16) {
                    *(__half2*)((__half*)C + (size_t)row * ldc + cn) =
                        __floats2half2_rn(v0, v1);
                } else {
                    float* crow = (float*)C + (size_t)row * ldc + cn;
                    crow[0] = v0; crow[1] = v1;
                }
            }
        }
    }
}

__global__ __launch_bounds__(256, 2)
void gemm_h_m128(const __half* __restrict__ A, int lda,
                 const __half* __restrict__ A2, int lda2, int ksplit,
                 const __half* __restrict__ Bm, int ldb,
                 void* __restrict__ C, int ldc,
                 const float* __restrict__ bias,
                 const float* __restrict__ resid, int ldr,
                 int K, float alpha, int flags)
{
    gemm_body<4>(A, lda, A2, lda2, ksplit, Bm, ldb, C, ldc,
                 bias, resid, ldr, K, alpha, flags,
                 blockIdx.y * 128, blockIdx.x * 128);
}

__global__ __launch_bounds__(256, 2)
void gemm_h_m64(const __half* __restrict__ A, int lda,
                const __half* __restrict__ A2, int lda2, int ksplit,
                const __half* __restrict__ Bm, int ldb,
                void* __restrict__ C, int ldc,
                const float* __restrict__ bias,
                const float* __restrict__ resid, int ldr,
                int K, float alpha, int flags)
{
    gemm_body<2>(A, lda, A2, lda2, ksplit, Bm, ldb, C, ldc,
                 bias, resid, ldr, K, alpha, flags,
                 blockIdx.y * 64, blockIdx.x * 128);
}

// ---- batched 4x (512x512x256) precompute GEMM -> fp16 out (proven R11) ----
struct GemmEntry { const __half* A; const __half* Bm; __half* C; int ldc; float alpha; };
struct GemmBatch4 { GemmEntry e[4]; };

__global__ __launch_bounds__(256, 2)
void gemm_h_b4(GemmBatch4 p)
{
    const GemmEntry& e = p.e[blockIdx.z];
    gemm_body<4>(e.A, 512, nullptr, 0, 0, e.Bm, 512, e.C, e.ldc,
                 nullptr, nullptr, 0, 256, e.alpha, FLAG_OUT16,
                 blockIdx.y * 128, blockIdx.x * 128);
}

// ---------------- flash attention: 512 threads, CHUNK=16 (proven math) -----
// Score warps: warp w -> head (w>>3), rows 2*(w&7)+rr. Accumulate: thread t
// -> head (t>>8), column pair (t&255). Softmax numerics identical to R11.
#define CHUNK 16
#define NCHUNK (N_ / CHUNK)                // 4
#define CHUNK_FLOATS (CHUNK * D_)          // 8192
#define ATTN_SMEM (2 * CHUNK_FLOATS * 4)   // 64 KB

__global__ __launch_bounds__(512)
void attention_kernel(const float* __restrict__ seq,
                      const void* __restrict__ mask,
                      const float* __restrict__ qt,   // [B,1024] fp32
                      __half* __restrict__ ctx,       // [B,1024] fp16
                      float* __restrict__ wout)       // [B,64]
{
    extern __shared__ float s_buf[];       // [2][CHUNK_FLOATS]
    __shared__ float s_all[128];
    __shared__ float s_m[2], s_l[2], s_f[2], s_e[2][CHUNK];
    __shared__ unsigned char s_mask[64];

    const int b = blockIdx.x, tid = threadIdx.x;
    const int warp = tid >> 5, lane = tid & 31;
    const float* sbp = seq + (size_t)b * N_ * D_;

    // this warp's score head and its q fragment (one head only -> 16 regs)
    const int hh = warp >> 3;
    float4 qf[4];
    {
        const float4* qp = (const float4*)(qt + (size_t)b * 1024 + hh * 512);
#pragma unroll
        for (int i = 0; i < 4; i++) qf[i] = qp[lane + 32 * i];
    }

    auto stage = [&](int c, int buf) {
        float* dst = s_buf + buf * CHUNK_FLOATS;
        const float* src = sbp + c * CHUNK_FLOATS;
#pragma unroll
        for (int i = 0; i < 4; i++) {
            const int e = (tid + 512 * i) * 4;
            cp16(dst + e, src + e);
        }
        asm volatile("cp.async.commit_group;" ::: "memory");
    };

    stage(0, 0);

    if (tid < 64) {
        unsigned int mv;
        if (g_mask_word) mv = ((const unsigned int*)mask)[(size_t)b * N_ + tid];
        else             mv = ((const unsigned char*)mask)[(size_t)b * N_ + tid];
        s_mask[tid] = (mv != 0u) ? 1 : 0;
    }
    if (tid < 2) { s_m[tid] = -3e38f; s_l[tid] = 0.f; }
    __syncthreads();

    const int ah = tid >> 8;       // accumulate head
    const int c2 = tid & 255;      // column pair
    float a0 = 0.f, a1 = 0.f;

    for (int c = 0; c < NCHUNK; c++) {
        const int buf = c & 1;
        asm volatile("cp.async.wait_group 0;" ::: "memory");
        __syncthreads();
        if (c < NCHUNK - 1) stage(c + 1, buf ^ 1);

        const float* rows = s_buf + buf * CHUNK_FLOATS;

        // scores: warp handles rows 2*(warp&7)+rr for head hh
#pragma unroll
        for (int rr = 0; rr < 2; rr++) {
            const int k = 2 * (warp & 7) + rr;
            const float4* r4 = (const float4*)(rows + k * D_);
            float a = 0.f;
#pragma unroll
            for (int i = 0; i < 4; i++) {
                float4 s = r4[lane + 32 * i];
                a += s.x * qf[i].x + s.y * qf[i].y + s.z * qf[i].z + s.w * qf[i].w;
            }
#pragma unroll
            for (int o = 16; o; o >>= 1) a += __shfl_xor_sync(0xffffffffu, a, o);
            if (lane == 0) {
                const int kg = c * CHUNK + k;
                s_all[hh * 64 + kg] = (s_mask[kg] != 0) ? -1e10f : a;
            }
        }
        __syncthreads();

        // online softmax update (warp 0 -> head 0, warp 1 -> head 1)
        if (warp < 2) {
            const int h = warp;
            float s = (lane < CHUNK) ? s_all[h * 64 + c * CHUNK + lane] : -3e38f;
            float cm = s;
#pragma unroll
            for (int o = 16; o; o >>= 1) cm = fmaxf(cm, __shfl_xor_sync(0xffffffffu, cm, o));
            const float m_old = s_m[h];
            const float m_new = fmaxf(m_old, cm);
            float e = (lane < CHUNK) ? __expf(s - m_new) : 0.f;
            float se = e;
#pragma unroll
            for (int o = 16; o; o >>= 1) se += __shfl_xor_sync(0xffffffffu, se, o);
            if (lane < CHUNK) s_e[h][lane] = e;
            if (lane == 0) {
                const float f = __expf(m_old - m_new);
                s_f[h] = f; s_m[h] = m_new;
                s_l[h] = s_l[h] * f + se;
            }
        }
        __syncthreads();

        // accumulate (one head per thread); no trailing sync — next wait+sync
        // orders buffer reuse.
        const float f = s_f[ah];
        a0 *= f; a1 *= f;
        const float2* rows2 = (const float2*)rows;
#pragma unroll
        for (int k = 0; k < CHUNK; k++) {
            float2 v = rows2[k * 256 + c2];
            const float e = s_e[ah][k];
            a0 += e * v.x; a1 += e * v.y;
        }
    }

    const float inv = 1.f / s_l[ah];
    __half2* orow = (__half2*)(ctx + (size_t)b * 1024);
    orow[ah * 256 + c2] = __floats2half2_rn(a0 * inv, a1 * inv);

    if (tid < 64) {
        const float inv0 = 1.f / s_l[0], inv1 = 1.f / s_l[1];
        const float at0 = __expf(s_all[tid]      - s_m[0]) * inv0;
        const float at1 = __expf(s_all[64 + tid] - s_m[1]) * inv1;
        wout[(size_t)b * 64 + tid] = 0.5f * (at0 + at1);
    }
}

// ---------------- layernorm (fp16 out: GEMM operand) ----------------
__global__ __launch_bounds__(128)
void ln_kernel(const float* __restrict__ x, const float* __restrict__ gam,
               const float* __restrict__ bet, __half* __restrict__ y)
{
    const int b = blockIdx.x, tid = threadIdx.x;
    const float* row = x + (size_t)b * 512;
    float v[4]; float s = 0.f;
#pragma unroll
    for (int j = 0; j < 4; j++) { v[j] = row[tid + 128 * j]; s += v[j]; }
    __shared__ float red[4];
#pragma unroll
    for (int o = 16; o; o >>= 1) s += __shfl_xor_sync(0xffffffffu, s, o);
    if ((tid & 31) == 0) red[tid >> 5] = s;
    __syncthreads();
    s = red[0] + red[1] + red[2] + red[3];
    const float mu = s * (1.f / 512.f);
    float var = 0.f;
#pragma unroll
    for (int j = 0; j < 4; j++) { float d = v[j] - mu; var += d * d; }
    __syncthreads();
#pragma unroll
    for (int o = 16; o; o >>= 1) var += __shfl_xor_sync(0xffffffffu, var, o);
    if ((tid & 31) == 0) red[tid >> 5] = var;
    __syncthreads();
    var = (red[0] + red[1] + red[2] + red[3]) * (1.f / 512.f);
    const float rs = rsqrtf(var + 1e-5f);
#pragma unroll
    for (int j = 0; j < 4; j++) {
        const int c = tid + 128 * j;
        y[(size_t)b * 512 + c] = __float2half_rn(gam[c] * (v[j] - mu) * rs + bet[c]);
    }
}

// ---------------- launch ----------------
extern "C" void kernel_launch(void* const* d_in, const int* in_sizes, int n_in,
                              void* d_out, int out_size)
{
    const float* src  = (const float*)d_in[0];
    const float* seq  = (const float*)d_in[1];
    const void*  mask = d_in[2];
    const float* Wq   = (const float*)d_in[3];
    const float* Wk   = (const float*)d_in[4];
    const float* Wv   = (const float*)d_in[5];
    const float* Wo   = (const float*)d_in[6];
    const float* bo   = (const float*)d_in[7];
    const float* ln_g = (const float*)d_in[8];
    const float* ln_b = (const float*)d_in[9];
    const float* W1   = (const float*)d_in[10];
    const float* b1   = (const float*)d_in[11];
    const float* W2   = (const float*)d_in[12];
    const float* b2   = (const float*)d_in[13];
    float* y    = (float*)d_out;                       // [B, 512]
    float* wout = (float*)d_out + (size_t)B_ * 512;    // [B, 64]

    __half *src_h, *Wq_h, *Wk_h, *Wv_h, *WoT, *W1T, *W2T, *CkT, *CvT, *CTX, *LN, *H1;
    float *QT, *PROJ;
    cudaGetSymbolAddress((void**)&src_h, g_src_h);
    cudaGetSymbolAddress((void**)&Wq_h,  g_Wq_h);
    cudaGetSymbolAddress((void**)&Wk_h,  g_Wk_h);
    cudaGetSymbolAddress((void**)&Wv_h,  g_Wv_h);
    cudaGetSymbolAddress((void**)&WoT,   g_WoT_h);
    cudaGetSymbolAddress((void**)&W1T,   g_W1T_h);
    cudaGetSymbolAddress((void**)&W2T,   g_W2T_h);
    cudaGetSymbolAddress((void**)&CkT,   g_CkT);
    cudaGetSymbolAddress((void**)&CvT,   g_CvT);
    cudaGetSymbolAddress((void**)&QT,    g_QT);
    cudaGetSymbolAddress((void**)&CTX,   g_CTX);
    cudaGetSymbolAddress((void**)&PROJ,  g_PROJ);
    cudaGetSymbolAddress((void**)&LN,    g_LN);
    cudaGetSymbolAddress((void**)&H1,    g_H1);

    cudaFuncSetAttribute(gemm_h_m128,
                         cudaFuncAttributeMaxDynamicSharedMemorySize, GEMM_SMEM_MF(4));
    cudaFuncSetAttribute(gemm_h_m64,
                         cudaFuncAttributeMaxDynamicSharedMemorySize, GEMM_SMEM_MF(2));
    cudaFuncSetAttribute(gemm_h_b4,
                         cudaFuncAttributeMaxDynamicSharedMemorySize, GEMM_SMEM_MF(4));
    cudaFuncSetAttribute(attention_kernel,
                         cudaFuncAttributeMaxDynamicSharedMemorySize, ATTN_SMEM);

    dim3 blk(256);

    detect_mask_kernel<<<1, 256>>>((const unsigned int*)mask);

    // pre-pass: fp16 copies (src, Wq, Wk, Wv)
    C16Batch cb;
    cb.e[0] = { (const float4*)src, (__half2*)src_h, B_ * 512 / 4 };
    cb.e[1] = { (const float4*)Wq,  (__half2*)Wq_h,  512 * 512 / 4 };
    cb.e[2] = { (const float4*)Wk,  (__half2*)Wk_h,  512 * 512 / 4 };
    cb.e[3] = { (const float4*)Wv,  (__half2*)Wv_h,  512 * 512 / 4 };
    cvt16_kernel<<<dim3(132, 1, 4), blk>>>(cb);

    // pre-pass: transposed fp16 (Wo, W1, W2)
    TrBatch tb;
    tb.e[0] = { Wo, WoT, 512, 512 };
    tb.e[1] = { W1, W1T, 1024, 512 };
    tb.e[2] = { W2, W2T, 512, 512 };
    transpose_cvt_kernel<<<dim3(16, 32, 3), blk>>>(tb);

    // precompute: CkT[h512+d][i] = (1/16) sum_k Wk[d,h256+k] Wq[i,h256+k]
    //             CvT[j][h512+i] =        sum_k WoT[j,h256+k] Wv[i,h256+k]
    GemmBatch4 pb;
    pb.e[0] = { Wk_h,       Wq_h,       CkT,                      512,  1.f / 16.f };
    pb.e[1] = { Wk_h + 256, Wq_h + 256, CkT + (size_t)512 * 512,  512,  1.f / 16.f };
    pb.e[2] = { WoT,        Wv_h,       CvT,                      1024, 1.f };
    pb.e[3] = { WoT + 256,  Wv_h + 256, CvT + 512,                1024, 1.f };
    gemm_h_b4<<<dim3(4, 4, 4), blk, GEMM_SMEM_MF(4)>>>(pb);

    // QT = src_h @ CkT^T (fp32 out)
    gemm_h_m128<<<dim3(8, 32), blk, GEMM_SMEM_MF(4)>>>(src_h, 512, nullptr, 0, 0,
                                    CkT, 512, QT, 1024,
                                    nullptr, nullptr, 0, 512, 1.f, 0);
    // flash attention (CTX fp16 out), 512 threads
    attention_kernel<<<B_, 512, ATTN_SMEM>>>(seq, mask, QT, CTX, wout);
    // PROJ = CTX @ CvT^T + bo + src (fp32 out)
    gemm_h_m64<<<dim3(4, 64), blk, GEMM_SMEM_MF(2)>>>(CTX, 1024, nullptr, 0, 0,
                                    CvT, 1024, PROJ, 512,
                                    bo, src, 512, 1024, 1.f, FLAG_BIAS | FLAG_RESID);
    // LayerNorm (fp16 out)
    ln_kernel<<<B_, 128>>>(PROJ, ln_g, ln_b, LN);
    // H1 = relu([LN | src_h] @ W1T^T + b1) (fp16 out)
    gemm_h_m64<<<dim3(4, 64), blk, GEMM_SMEM_MF(2)>>>(LN, 512, src_h, 512, 512,
                                    W1T, 1024, H1, 512,
                                    b1, nullptr, 0, 1024, 1.f,
                                    FLAG_BIAS | FLAG_RELU | FLAG_OUT16);
    // y = H1 @ W2T^T + b2 (fp32 out)
    gemm_h_m64<<<dim3(4, 64), blk, GEMM_SMEM_MF(2)>>>(H1, 512, nullptr, 0, 0,
                                    W2T, 512, y, 512,
                                    b2, nullptr, 0, 512, 1.f, FLAG_BIAS);
}

// round 15
// speedup vs baseline: 1.1518x; 1.1518x over previous
#include <cuda_runtime.h>
#include <cuda_fp16.h>
#include <cstdint>

// Shapes (fixed for this problem)
#define B_ 4096
#define N_ 64
#define D_ 512
#define H_ 2
#define DK_ 256

// ---------------- scratch (static device arrays; no allocs) ----------------
__device__ __align__(16) __half g_src_h[(size_t)B_ * 512];
__device__ __align__(16) __half g_Wq_h[512 * 512];
__device__ __align__(16) __half g_Wk_h[512 * 512];
__device__ __align__(16) __half g_Wv_h[512 * 512];
__device__ __align__(16) __half g_WoT_h[512 * 512];          // Wo^T
__device__ __align__(16) __half g_W1T_h[512 * 1024];         // W1^T
__device__ __align__(16) __half g_W2T_h[512 * 512];          // W2^T
__device__ __align__(16) __half g_CkT[1024 * 512];           // CkT[c][i]
__device__ __align__(16) __half g_CvT[512 * 1024];           // CvT[j][c]
__device__ __align__(16) float  g_QT[(size_t)B_ * 1024];
__device__ __align__(16) __half g_CTX[(size_t)B_ * 1024];
__device__ __align__(16) float  g_PROJ[(size_t)B_ * 512];
__device__ __align__(16) __half g_LN[(size_t)B_ * 512];
__device__ __align__(16) __half g_H1[(size_t)B_ * 512];
__device__ int g_mask_word;   // 1 = 4-byte mask elements, 0 = 1-byte

// ---------------- helpers ----------------
__device__ __forceinline__ void cp16(void* s, const void* g)
{
    uint32_t sa = (uint32_t)__cvta_generic_to_shared(s);
    asm volatile("cp.async.cg.shared.global [%0], [%1], 16;" :: "r"(sa), "l"(g));
}
__device__ __forceinline__ void ldsm_x4(uint32_t& r0, uint32_t& r1,
                                        uint32_t& r2, uint32_t& r3, const void* p)
{
    uint32_t a = (uint32_t)__cvta_generic_to_shared(p);
    asm volatile("ldmatrix.sync.aligned.m8n8.x4.shared.b16 {%0,%1,%2,%3}, [%4];"
                 : "=r"(r0), "=r"(r1), "=r"(r2), "=r"(r3) : "r"(a));
}

// ---------------- mask dtype detection ----------------
__global__ void detect_mask_kernel(const unsigned int* __restrict__ m)
{
    __shared__ int bad;
    if (threadIdx.x == 0) bad = 0;
    __syncthreads();
    unsigned int w = m[threadIdx.x];
    if (!(w == 0u || w == 1u || w == 0x3F800000u)) atomicOr(&bad, 1);
    __syncthreads();
    if (threadIdx.x == 0) g_mask_word = bad ? 0 : 1;
}

// ---------------- pre-pass: fp16 copies + transposes ----------------
struct C16Entry { const float4* s; __half2* d; int n4; };
struct C16Batch { C16Entry e[4]; };
__global__ __launch_bounds__(256)
void cvt16_kernel(C16Batch p)
{
    const C16Entry& e = p.e[blockIdx.z];
    for (int i = blockIdx.x * 256 + threadIdx.x; i < e.n4; i += gridDim.x * 256) {
        float4 v = e.s[i];
        e.d[2 * i]     = __floats2half2_rn(v.x, v.y);
        e.d[2 * i + 1] = __floats2half2_rn(v.z, v.w);
    }
}

struct TrEntry { const float* s; __half* d; int rows, cols; };
struct TrBatch { TrEntry e[3]; };
__global__ __launch_bounds__(256)
void transpose_cvt_kernel(TrBatch p)
{
    const TrEntry& e = p.e[blockIdx.z];
    const int c0 = blockIdx.x * 32, r0 = blockIdx.y * 32;
    if (c0 >= e.cols || r0 >= e.rows) return;
    __shared__ float t[32][33];
    const int x = threadIdx.x & 31, y = threadIdx.x >> 5;  // 32 x 8
#pragma unroll
    for (int j = 0; j < 32; j += 8)
        t[y + j][x] = e.s[(size_t)(r0 + y + j) * e.cols + c0 + x];
    __syncthreads();
#pragma unroll
    for (int j = 0; j < 32; j += 8)
        e.d[(size_t)(c0 + y + j) * e.rows + r0 + x] = __float2half_rn(t[x][y + j]);
}

// ---------------- fp16 tensor-core GEMM (cp.async 3-stage, ldmatrix) --------
#define FLAG_BIAS  1
#define FLAG_RELU  2
#define FLAG_RESID 4
#define FLAG_OUT16 8

#define A_STRIDE_H 40                          // halves per SMEM row (32 used)
#define BBUF_H (128 * A_STRIDE_H)
#define GEMM_SMEM_MF(MF) (3 * ((MF) * 32 * A_STRIDE_H + BBUF_H) * 2)

template<int MF>   // CTA rows = MF*32
__device__ __forceinline__ void gemm_body(
    const __half* __restrict__ A, int lda,
    const __half* __restrict__ A2, int lda2, int ksplit,
    const __half* __restrict__ Bm, int ldb,
    void* __restrict__ C, int ldc,
    const float* __restrict__ bias,
    const float* __restrict__ resid, int ldr,
    int K, float alpha, int flags, int bm, int bn)
{
    constexpr int ABUF = MF * 32 * A_STRIDE_H;
    extern __shared__ __half smh[];
    __half* Asf = smh;                    // [3][MF*32 * A_STRIDE_H]
    __half* Bsf = smh + 3 * ABUF;         // [3][128 * A_STRIDE_H]

    const int tid = threadIdx.x;
    const int warp = tid >> 5, lane = tid & 31;
    const int wm = warp >> 2, wn = warp & 3;
    const int gid = lane >> 2, tig = lane & 3;

    const int a_row_l = (lane & 7) + ((lane >> 3) & 1) * 8;
    const int a_col_l = ((lane >> 4) & 1) * 8;
    const int b_row_l = ((lane >> 4) & 1) * 8 + (lane & 7);
    const int b_col_l = ((lane >> 3) & 1) * 8;

    float c[MF][4][4];
#pragma unroll
    for (int i = 0; i < MF; i++)
#pragma unroll
        for (int j = 0; j < 4; j++)
#pragma unroll
            for (int r = 0; r < 4; r++) c[i][j][r] = 0.f;

    const int KT = K >> 5;

    auto stage = [&](int kt, int slot) {
        const int k0 = kt * 32;
        __half* As = Asf + slot * ABUF;
        __half* Bs = Bsf + slot * BBUF_H;
#pragma unroll
        for (int j = 0; j < MF / 2; j++) {
            const int i = tid + 256 * j;
            const int row = i >> 2, c16 = i & 3;
            const int kg = k0 + c16 * 8;
            const __half* ap = (A2 != nullptr && kg >= ksplit)
                ? (A2 + (size_t)(bm + row) * lda2 + (kg - ksplit))
                : (A  + (size_t)(bm + row) * lda  + kg);
            cp16(As + row * A_STRIDE_H + c16 * 8, ap);
        }
#pragma unroll
        for (int j = 0; j < 2; j++) {
            const int i = tid + 256 * j;
            const int row = i >> 2, c16 = i & 3;
            cp16(Bs + row * A_STRIDE_H + c16 * 8,
                 Bm + (size_t)(bn + row) * ldb + k0 + c16 * 8);
        }
        asm volatile("cp.async.commit_group;" ::: "memory");
    };

    stage(0, 0);
    if (KT > 1) stage(1, 1);

    int slot = 0;
    for (int kt = 0; kt < KT; kt++) {
        asm volatile("cp.async.wait_group 1;" ::: "memory");
        __syncthreads();
        if (kt + 2 < KT) {
            int ns = slot + 2; if (ns >= 3) ns -= 3;
            stage(kt + 2, ns);
        }

        const __half* As = Asf + slot * ABUF;
        const __half* Bs = Bsf + slot * BBUF_H;
#pragma unroll
        for (int ks = 0; ks < 2; ks++) {
            uint32_t a[MF][4], b[4][2];
#pragma unroll
            for (int mf = 0; mf < MF; mf++) {
                const int r = wm * (MF * 16) + mf * 16 + a_row_l;
                ldsm_x4(a[mf][0], a[mf][1], a[mf][2], a[mf][3],
                        As + r * A_STRIDE_H + ks * 16 + a_col_l);
            }
#pragma unroll
            for (int nfp = 0; nfp < 2; nfp++) {
                const int cn = wn * 32 + nfp * 16 + b_row_l;
                ldsm_x4(b[2 * nfp][0], b[2 * nfp][1], b[2 * nfp + 1][0], b[2 * nfp + 1][1],
                        Bs + cn * A_STRIDE_H + ks * 16 + b_col_l);
            }
#pragma unroll
            for (int mf = 0; mf < MF; mf++)
#pragma unroll
                for (int nf = 0; nf < 4; nf++)
                    asm volatile(
                        "mma.sync.aligned.m16n8k16.row.col.f32.f16.f16.f32 "
                        "{%0,%1,%2,%3}, {%4,%5,%6,%7}, {%8,%9}, {%0,%1,%2,%3};"
                        : "+f"(c[mf][nf][0]), "+f"(c[mf][nf][1]),
                          "+f"(c[mf][nf][2]), "+f"(c[mf][nf][3])
                        : "r"(a[mf][0]), "r"(a[mf][1]), "r"(a[mf][2]), "r"(a[mf][3]),
                          "r"(b[nf][0]), "r"(b[nf][1]));
        }
        slot++; if (slot == 3) slot = 0;
    }

    // ---- epilogue ----
#pragma unroll
    for (int mf = 0; mf < MF; mf++) {
        const int r0 = bm + wm * (MF * 16) + mf * 16 + gid;
#pragma unroll
        for (int nf = 0; nf < 4; nf++) {
            const int cn = bn + wn * 32 + nf * 8 + tig * 2;
#pragma unroll
            for (int half = 0; half < 2; half++) {
                const int row = r0 + half * 8;
                float v0 = c[mf][nf][half * 2 + 0] * alpha;
                float v1 = c[mf][nf][half * 2 + 1] * alpha;
                if (flags & FLAG_BIAS)  { v0 += bias[cn]; v1 += bias[cn + 1]; }
                if (flags & FLAG_RESID) {
                    v0 += resid[(size_t)row * ldr + cn];
                    v1 += resid[(size_t)row * ldr + cn + 1];
                }
                if (flags & FLAG_RELU)  { v0 = fmaxf(v0, 0.f); v1 = fmaxf(v1, 0.f); }
                if (flags & FLAG_OUT16) {
                    *(__half2*)((__half*)C + (size_t)row * ldc + cn) =
                        __floats2half2_rn(v0, v1);
                } else {
                    float* crow = (float*)C + (size_t)row * ldc + cn;
                    crow[0] = v0; crow[1] = v1;
                }
            }
        }
    }
}

__global__ __launch_bounds__(256, 2)
void gemm_h_m128(const __half* __restrict__ A, int lda,
                 const __half* __restrict__ A2, int lda2, int ksplit,
                 const __half* __restrict__ Bm, int ldb,
                 void* __restrict__ C, int ldc,
                 const float* __restrict__ bias,
                 const float* __restrict__ resid, int ldr,
                 int K, float alpha, int flags)
{
    gemm_body<4>(A, lda, A2, lda2, ksplit, Bm, ldb, C, ldc,
                 bias, resid, ldr, K, alpha, flags,
                 blockIdx.y * 128, blockIdx.x * 128);
}

__global__ __launch_bounds__(256, 2)
void gemm_h_m64(const __half* __restrict__ A, int lda,
                const __half* __restrict__ A2, int lda2, int ksplit,
                const __half* __restrict__ Bm, int ldb,
                void* __restrict__ C, int ldc,
                const float* __restrict__ bias,
                const float* __restrict__ resid, int ldr,
                int K, float alpha, int flags)
{
    gemm_body<2>(A, lda, A2, lda2, ksplit, Bm, ldb, C, ldc,
                 bias, resid, ldr, K, alpha, flags,
                 blockIdx.y * 64, blockIdx.x * 128);
}

// ---- batched 4x (512x512x256) precompute GEMM -> fp16 out (proven R11) ----
struct GemmEntry { const __half* A; const __half* Bm; __half* C; int ldc; float alpha; };
struct GemmBatch4 { GemmEntry e[4]; };

__global__ __launch_bounds__(256, 2)
void gemm_h_b4(GemmBatch4 p)
{
    const GemmEntry& e = p.e[blockIdx.z];
    gemm_body<4>(e.A, 512, nullptr, 0, 0, e.Bm, 512, e.C, e.ldc,
                 nullptr, nullptr, 0, 256, e.alpha, FLAG_OUT16,
                 blockIdx.y * 128, blockIdx.x * 128);
}

// ---------------- flash attention: 256 threads, CHUNK=8 (isolated change) --
// 2 x 16KB buffers -> 32 KB SMEM -> up to 6 CTAs/SM residency.
#define CHUNK 8
#define NCHUNK (N_ / CHUNK)                // 8
#define CHUNK_FLOATS (CHUNK * D_)          // 4096
#define ATTN_SMEM (2 * CHUNK_FLOATS * 4)   // 32 KB

__global__ __launch_bounds__(256)
void attention_kernel(const float* __restrict__ seq,
                      const void* __restrict__ mask,
                      const float* __restrict__ qt,   // [B,1024] fp32
                      __half* __restrict__ ctx,       // [B,1024] fp16
                      float* __restrict__ wout)       // [B,64]
{
    extern __shared__ float s_buf[];       // [2][CHUNK_FLOATS]
    __shared__ float s_all[128];
    __shared__ float s_m[2], s_l[2], s_f[2], s_e[2][CHUNK];
    __shared__ unsigned char s_mask[64];

    const int b = blockIdx.x, tid = threadIdx.x;
    const int warp = tid >> 5, lane = tid & 31;
    const float* sbp = seq + (size_t)b * N_ * D_;

    float4 q0f[4], q1f[4];
    {
        const float4* q0p = (const float4*)(qt + (size_t)b * 1024);
        const float4* q1p = q0p + 128;
#pragma unroll
        for (int i = 0; i < 4; i++) {
            q0f[i] = q0p[lane + 32 * i];
            q1f[i] = q1p[lane + 32 * i];
        }
    }

    auto stage = [&](int c, int buf) {
        float* dst = s_buf + buf * CHUNK_FLOATS;
        const float* src = sbp + c * CHUNK_FLOATS;
#pragma unroll
        for (int i = 0; i < 4; i++) {
            const int e = (tid + 256 * i) * 4;
            cp16(dst + e, src + e);
        }
        asm volatile("cp.async.commit_group;" ::: "memory");
    };

    stage(0, 0);

    if (tid < 64) {
        unsigned int mv;
        if (g_mask_word) mv = ((const unsigned int*)mask)[(size_t)b * N_ + tid];
        else             mv = ((const unsigned char*)mask)[(size_t)b * N_ + tid];
        s_mask[tid] = (mv != 0u) ? 1 : 0;
    }
    if (tid < 2) { s_m[tid] = -3e38f; s_l[tid] = 0.f; }
    __syncthreads();

    float a00 = 0.f, a01 = 0.f, a10 = 0.f, a11 = 0.f;

    for (int c = 0; c < NCHUNK; c++) {
        const int buf = c & 1;
        asm volatile("cp.async.wait_group 0;" ::: "memory");
        __syncthreads();
        if (c < NCHUNK - 1) stage(c + 1, buf ^ 1);

        const float* rows = s_buf + buf * CHUNK_FLOATS;

        // scores: warp w handles chunk row w (both heads)
        {
            const int k = warp;
            const float4* r4 = (const float4*)(rows + k * D_);
            float a0 = 0.f, a1 = 0.f;
#pragma unroll
            for (int i = 0; i < 4; i++) {
                float4 s = r4[lane + 32 * i];
                a0 += s.x * q0f[i].x + s.y * q0f[i].y + s.z * q0f[i].z + s.w * q0f[i].w;
                a1 += s.x * q1f[i].x + s.y * q1f[i].y + s.z * q1f[i].z + s.w * q1f[i].w;
            }
#pragma unroll
            for (int o = 16; o; o >>= 1) {
                a0 += __shfl_xor_sync(0xffffffffu, a0, o);
                a1 += __shfl_xor_sync(0xffffffffu, a1, o);
            }
            if (lane == 0) {
                const int kg = c * CHUNK + k;
                const bool mk = s_mask[kg] != 0;
                s_all[kg]      = mk ? -1e10f : a0;
                s_all[64 + kg] = mk ? -1e10f : a1;
            }
        }
        __syncthreads();

        // online softmax update (warp 0 -> head 0, warp 1 -> head 1)
        if (warp < 2) {
            const int h = warp;
            float s = (lane < CHUNK) ? s_all[h * 64 + c * CHUNK + lane] : -3e38f;
            float cm = s;
#pragma unroll
            for (int o = 16; o; o >>= 1) cm = fmaxf(cm, __shfl_xor_sync(0xffffffffu, cm, o));
            const float m_old = s_m[h];
            const float m_new = fmaxf(m_old, cm);
            float e = (lane < CHUNK) ? __expf(s - m_new) : 0.f;
            float se = e;
#pragma unroll
            for (int o = 16; o; o >>= 1) se += __shfl_xor_sync(0xffffffffu, se, o);
            if (lane < CHUNK) s_e[h][lane] = e;
            if (lane == 0) {
                const float f = __expf(m_old - m_new);
                s_f[h] = f; s_m[h] = m_new;
                s_l[h] = s_l[h] * f + se;
            }
        }
        __syncthreads();

        // accumulate: thread owns cols (2*tid, 2*tid+1); no trailing sync
        const float f0 = s_f[0], f1 = s_f[1];
        a00 *= f0; a01 *= f0; a10 *= f1; a11 *= f1;
        const float2* rows2 = (const float2*)rows;
#pragma unroll
        for (int k = 0; k < CHUNK; k++) {
            float2 v = rows2[k * 256 + tid];
            const float e0 = s_e[0][k], e1 = s_e[1][k];
            a00 += e0 * v.x; a01 += e0 * v.y;
            a10 += e1 * v.x; a11 += e1 * v.y;
        }
    }

    const float inv0 = 1.f / s_l[0], inv1 = 1.f / s_l[1];
    __half2* orow = (__half2*)(ctx + (size_t)b * 1024);
    orow[tid]       = __floats2half2_rn(a00 * inv0, a01 * inv0);
    orow[256 + tid] = __floats2half2_rn(a10 * inv1, a11 * inv1);

    if (tid < 64) {
        const float m0 = s_m[0], m1 = s_m[1];
        const float at0 = __expf(s_all[tid]      - m0) * inv0;
        const float at1 = __expf(s_all[64 + tid] - m1) * inv1;
        wout[(size_t)b * 64 + tid] = 0.5f * (at0 + at1);
    }
}

// ---------------- layernorm (fp16 out: GEMM operand) ----------------
__global__ __launch_bounds__(128)
void ln_kernel(const float* __restrict__ x, const float* __restrict__ gam,
               const float* __restrict__ bet, __half* __restrict__ y)
{
    const int b = blockIdx.x, tid = threadIdx.x;
    const float* row = x + (size_t)b * 512;
    float v[4]; float s = 0.f;
#pragma unroll
    for (int j = 0; j < 4; j++) { v[j] = row[tid + 128 * j]; s += v[j]; }
    __shared__ float red[4];
#pragma unroll
    for (int o = 16; o; o >>= 1) s += __shfl_xor_sync(0xffffffffu, s, o);
    if ((tid & 31) == 0) red[tid >> 5] = s;
    __syncthreads();
    s = red[0] + red[1] + red[2] + red[3];
    const float mu = s * (1.f / 512.f);
    float var = 0.f;
#pragma unroll
    for (int j = 0; j < 4; j++) { float d = v[j] - mu; var += d * d; }
    __syncthreads();
#pragma unroll
    for (int o = 16; o; o >>= 1) var += __shfl_xor_sync(0xffffffffu, var, o);
    if ((tid & 31) == 0) red[tid >> 5] = var;
    __syncthreads();
    var = (red[0] + red[1] + red[2] + red[3]) * (1.f / 512.f);
    const float rs = rsqrtf(var + 1e-5f);
#pragma unroll
    for (int j = 0; j < 4; j++) {
        const int c = tid + 128 * j;
        y[(size_t)b * 512 + c] = __float2half_rn(gam[c] * (v[j] - mu) * rs + bet[c]);
    }
}

// ---------------- launch ----------------
extern "C" void kernel_launch(void* const* d_in, const int* in_sizes, int n_in,
                              void* d_out, int out_size)
{
    const float* src  = (const float*)d_in[0];
    const float* seq  = (const float*)d_in[1];
    const void*  mask = d_in[2];
    const float* Wq   = (const float*)d_in[3];
    const float* Wk   = (const float*)d_in[4];
    const float* Wv   = (const float*)d_in[5];
    const float* Wo   = (const float*)d_in[6];
    const float* bo   = (const float*)d_in[7];
    const float* ln_g = (const float*)d_in[8];
    const float* ln_b = (const float*)d_in[9];
    const float* W1   = (const float*)d_in[10];
    const float* b1   = (const float*)d_in[11];
    const float* W2   = (const float*)d_in[12];
    const float* b2   = (const float*)d_in[13];
    float* y    = (float*)d_out;                       // [B, 512]
    float* wout = (float*)d_out + (size_t)B_ * 512;    // [B, 64]

    __half *src_h, *Wq_h, *Wk_h, *Wv_h, *WoT, *W1T, *W2T, *CkT, *CvT, *CTX, *LN, *H1;
    float *QT, *PROJ;
    cudaGetSymbolAddress((void**)&src_h, g_src_h);
    cudaGetSymbolAddress((void**)&Wq_h,  g_Wq_h);
    cudaGetSymbolAddress((void**)&Wk_h,  g_Wk_h);
    cudaGetSymbolAddress((void**)&Wv_h,  g_Wv_h);
    cudaGetSymbolAddress((void**)&WoT,   g_WoT_h);
    cudaGetSymbolAddress((void**)&W1T,   g_W1T_h);
    cudaGetSymbolAddress((void**)&W2T,   g_W2T_h);
    cudaGetSymbolAddress((void**)&CkT,   g_CkT);
    cudaGetSymbolAddress((void**)&CvT,   g_CvT);
    cudaGetSymbolAddress((void**)&QT,    g_QT);
    cudaGetSymbolAddress((void**)&CTX,   g_CTX);
    cudaGetSymbolAddress((void**)&PROJ,  g_PROJ);
    cudaGetSymbolAddress((void**)&LN,    g_LN);
    cudaGetSymbolAddress((void**)&H1,    g_H1);

    cudaFuncSetAttribute(gemm_h_m128,
                         cudaFuncAttributeMaxDynamicSharedMemorySize, GEMM_SMEM_MF(4));
    cudaFuncSetAttribute(gemm_h_m64,
                         cudaFuncAttributeMaxDynamicSharedMemorySize, GEMM_SMEM_MF(2));
    cudaFuncSetAttribute(gemm_h_b4,
                         cudaFuncAttributeMaxDynamicSharedMemorySize, GEMM_SMEM_MF(4));
    cudaFuncSetAttribute(attention_kernel,
                         cudaFuncAttributeMaxDynamicSharedMemorySize, ATTN_SMEM);

    dim3 blk(256);

    detect_mask_kernel<<<1, 256>>>((const unsigned int*)mask);

    // pre-pass: fp16 copies (src, Wq, Wk, Wv)
    C16Batch cb;
    cb.e[0] = { (const float4*)src, (__half2*)src_h, B_ * 512 / 4 };
    cb.e[1] = { (const float4*)Wq,  (__half2*)Wq_h,  512 * 512 / 4 };
    cb.e[2] = { (const float4*)Wk,  (__half2*)Wk_h,  512 * 512 / 4 };
    cb.e[3] = { (const float4*)Wv,  (__half2*)Wv_h,  512 * 512 / 4 };
    cvt16_kernel<<<dim3(132, 1, 4), blk>>>(cb);

    // pre-pass: transposed fp16 (Wo, W1, W2)
    TrBatch tb;
    tb.e[0] = { Wo, WoT, 512, 512 };
    tb.e[1] = { W1, W1T, 1024, 512 };
    tb.e[2] = { W2, W2T, 512, 512 };
    transpose_cvt_kernel<<<dim3(16, 32, 3), blk>>>(tb);

    // precompute: CkT[h512+d][i] = (1/16) sum_k Wk[d,h256+k] Wq[i,h256+k]
    //             CvT[j][h512+i] =        sum_k WoT[j,h256+k] Wv[i,h256+k]
    GemmBatch4 pb;
    pb.e[0] = { Wk_h,       Wq_h,       CkT,                      512,  1.f / 16.f };
    pb.e[1] = { Wk_h + 256, Wq_h + 256, CkT + (size_t)512 * 512,  512,  1.f / 16.f };
    pb.e[2] = { WoT,        Wv_h,       CvT,                      1024, 1.f };
    pb.e[3] = { WoT + 256,  Wv_h + 256, CvT + 512,                1024, 1.f };
    gemm_h_b4<<<dim3(4, 4, 4), blk, GEMM_SMEM_MF(4)>>>(pb);

    // QT = src_h @ CkT^T (fp32 out)
    gemm_h_m128<<<dim3(8, 32), blk, GEMM_SMEM_MF(4)>>>(src_h, 512, nullptr, 0, 0,
                                    CkT, 512, QT, 1024,
                                    nullptr, nullptr, 0, 512, 1.f, 0);
    // flash attention (CTX fp16 out), 256 threads, CHUNK=8
    attention_kernel<<<B_, 256, ATTN_SMEM>>>(seq, mask, QT, CTX, wout);
    // PROJ = CTX @ CvT^T + bo + src (fp32 out)
    gemm_h_m64<<<dim3(4, 64), blk, GEMM_SMEM_MF(2)>>>(CTX, 1024, nullptr, 0, 0,
                                    CvT, 1024, PROJ, 512,
                                    bo, src, 512, 1024, 1.f, FLAG_BIAS | FLAG_RESID);
    // LayerNorm (fp16 out)
    ln_kernel<<<B_, 128>>>(PROJ, ln_g, ln_b, LN);
    // H1 = relu([LN | src_h] @ W1T^T + b1) (fp16 out)
    gemm_h_m64<<<dim3(4, 64), blk, GEMM_SMEM_MF(2)>>>(LN, 512, src_h, 512, 512,
                                    W1T, 1024, H1, 512,
                                    b1, nullptr, 0, 1024, 1.f,
                                    FLAG_BIAS | FLAG_RELU | FLAG_OUT16);
    // y = H1 @ W2T^T + b2 (fp32 out)
    gemm_h_m64<<<dim3(4, 64), blk, GEMM_SMEM_MF(2)>>>(H1, 512, nullptr, 0, 0,
                                    W2T, 512, y, 512,
                                    b2, nullptr, 0, 512, 1.f, FLAG_BIAS);
}

// round 16
// speedup vs baseline: 1.2447x; 1.0807x over previous
#include <cuda_runtime.h>
#include <cuda_fp16.h>
#include <cstdint>

// Shapes (fixed for this problem)
#define B_ 4096
#define N_ 64
#define D_ 512
#define H_ 2
#define DK_ 256

// ---------------- scratch (static device arrays; no allocs) ----------------
__device__ __align__(16) __half g_src_h[(size_t)B_ * 512];
__device__ __align__(16) __half g_Wq_h[512 * 512];
__device__ __align__(16) __half g_Wk_h[512 * 512];
__device__ __align__(16) __half g_Wv_h[512 * 512];
__device__ __align__(16) __half g_WoT_h[512 * 512];          // Wo^T
__device__ __align__(16) __half g_W1T_h[512 * 1024];         // W1^T
__device__ __align__(16) __half g_W2T_h[512 * 512];          // W2^T
__device__ __align__(16) __half g_CkT[1024 * 512];           // CkT[c][i]
__device__ __align__(16) __half g_CvT[512 * 1024];           // CvT[j][c]
__device__ __align__(16) float  g_QT[(size_t)B_ * 1024];
__device__ __align__(16) __half g_CTX[(size_t)B_ * 1024];
__device__ __align__(16) float  g_PROJ[(size_t)B_ * 512];
__device__ __align__(16) __half g_LN[(size_t)B_ * 512];
__device__ __align__(16) __half g_H1[(size_t)B_ * 512];
__device__ int g_mask_word;   // 1 = 4-byte mask elements, 0 = 1-byte

// ---------------- helpers ----------------
__device__ __forceinline__ void cp16(void* s, const void* g)
{
    uint32_t sa = (uint32_t)__cvta_generic_to_shared(s);
    asm volatile("cp.async.cg.shared.global [%0], [%1], 16;" :: "r"(sa), "l"(g));
}
__device__ __forceinline__ void ldsm_x4(uint32_t& r0, uint32_t& r1,
                                        uint32_t& r2, uint32_t& r3, const void* p)
{
    uint32_t a = (uint32_t)__cvta_generic_to_shared(p);
    asm volatile("ldmatrix.sync.aligned.m8n8.x4.shared.b16 {%0,%1,%2,%3}, [%4];"
                 : "=r"(r0), "=r"(r1), "=r"(r2), "=r"(r3) : "r"(a));
}

// ---------------- fused pre-pass: detect + fp16 copies + transposes --------
// z < 4  : cvt16 entry z (x strided over n4)
// z 4..6 : transpose entry z-4 (tile id = y*gridDim.x + x)
// z == 7 : mask dtype detection (block (0,0) only)
struct C16Entry { const float4* s; __half2* d; int n4; };
struct TrEntry  { const float* s; __half* d; int rows, cols; };
struct PrepassArgs {
    C16Entry c[4];
    TrEntry  t[3];
    const unsigned int* mask;
};

__global__ __launch_bounds__(256)
void prepass_kernel(PrepassArgs p)
{
    const int z = blockIdx.z;
    if (z < 4) {
        const C16Entry& e = p.c[z];
        const int stride = gridDim.x * gridDim.y * 256;
        for (int i = (blockIdx.y * gridDim.x + blockIdx.x) * 256 + threadIdx.x;
             i < e.n4; i += stride) {
            float4 v = e.s[i];
            e.d[2 * i]     = __floats2half2_rn(v.x, v.y);
            e.d[2 * i + 1] = __floats2half2_rn(v.z, v.w);
        }
    } else if (z < 7) {
        const TrEntry& e = p.t[z - 4];
        const int tile = blockIdx.y * gridDim.x + blockIdx.x;
        const int ctiles = e.cols >> 5;
        const int c0 = (tile % ctiles) * 32, r0 = (tile / ctiles) * 32;
        if (r0 >= e.rows) return;
        __shared__ float t[32][33];
        const int x = threadIdx.x & 31, y = threadIdx.x >> 5;  // 32 x 8
#pragma unroll
        for (int j = 0; j < 32; j += 8)
            t[y + j][x] = e.s[(size_t)(r0 + y + j) * e.cols + c0 + x];
        __syncthreads();
#pragma unroll
        for (int j = 0; j < 32; j += 8)
            e.d[(size_t)(c0 + y + j) * e.rows + r0 + x] = __float2half_rn(t[x][y + j]);
    } else if (blockIdx.x == 0 && blockIdx.y == 0) {
        __shared__ int bad;
        if (threadIdx.x == 0) bad = 0;
        __syncthreads();
        unsigned int w = p.mask[threadIdx.x];
        if (!(w == 0u || w == 1u || w == 0x3F800000u)) atomicOr(&bad, 1);
        __syncthreads();
        if (threadIdx.x == 0) g_mask_word = bad ? 0 : 1;
    }
}

// ---------------- fp16 tensor-core GEMM (cp.async 3-stage, ldmatrix) --------
#define FLAG_BIAS  1
#define FLAG_RELU  2
#define FLAG_RESID 4
#define FLAG_OUT16 8

#define A_STRIDE_H 40                          // halves per SMEM row (32 used)
#define BBUF_H (128 * A_STRIDE_H)
#define GEMM_SMEM_MF(MF) (3 * ((MF) * 32 * A_STRIDE_H + BBUF_H) * 2)

template<int MF>   // CTA rows = MF*32
__device__ __forceinline__ void gemm_body(
    const __half* __restrict__ A, int lda,
    const __half* __restrict__ A2, int lda2, int ksplit,
    const __half* __restrict__ Bm, int ldb,
    void* __restrict__ C, int ldc,
    const float* __restrict__ bias,
    const float* __restrict__ resid, int ldr,
    int K, float alpha, int flags, int bm, int bn)
{
    constexpr int ABUF = MF * 32 * A_STRIDE_H;
    extern __shared__ __half smh[];
    __half* Asf = smh;                    // [3][MF*32 * A_STRIDE_H]
    __half* Bsf = smh + 3 * ABUF;         // [3][128 * A_STRIDE_H]

    const int tid = threadIdx.x;
    const int warp = tid >> 5, lane = tid & 31;
    const int wm = warp >> 2, wn = warp & 3;
    const int gid = lane >> 2, tig = lane & 3;

    const int a_row_l = (lane & 7) + ((lane >> 3) & 1) * 8;
    const int a_col_l = ((lane >> 4) & 1) * 8;
    const int b_row_l = ((lane >> 4) & 1) * 8 + (lane & 7);
    const int b_col_l = ((lane >> 3) & 1) * 8;

    float c[MF][4][4];
#pragma unroll
    for (int i = 0; i < MF; i++)
#pragma unroll
        for (int j = 0; j < 4; j++)
#pragma unroll
            for (int r = 0; r < 4; r++) c[i][j][r] = 0.f;

    const int KT = K >> 5;

    auto stage = [&](int kt, int slot) {
        const int k0 = kt * 32;
        __half* As = Asf + slot * ABUF;
        __half* Bs = Bsf + slot * BBUF_H;
#pragma unroll
        for (int j = 0; j < MF / 2; j++) {
            const int i = tid + 256 * j;
            const int row = i >> 2, c16 = i & 3;
            const int kg = k0 + c16 * 8;
            const __half* ap = (A2 != nullptr && kg >= ksplit)
                ? (A2 + (size_t)(bm + row) * lda2 + (kg - ksplit))
                : (A  + (size_t)(bm + row) * lda  + kg);
            cp16(As + row * A_STRIDE_H + c16 * 8, ap);
        }
#pragma unroll
        for (int j = 0; j < 2; j++) {
            const int i = tid + 256 * j;
            const int row = i >> 2, c16 = i & 3;
            cp16(Bs + row * A_STRIDE_H + c16 * 8,
                 Bm + (size_t)(bn + row) * ldb + k0 + c16 * 8);
        }
        asm volatile("cp.async.commit_group;" ::: "memory");
    };

    stage(0, 0);
    if (KT > 1) stage(1, 1);

    int slot = 0;
    for (int kt = 0; kt < KT; kt++) {
        asm volatile("cp.async.wait_group 1;" ::: "memory");
        __syncthreads();
        if (kt + 2 < KT) {
            int ns = slot + 2; if (ns >= 3) ns -= 3;
            stage(kt + 2, ns);
        }

        const __half* As = Asf + slot * ABUF;
        const __half* Bs = Bsf + slot * BBUF_H;
#pragma unroll
        for (int ks = 0; ks < 2; ks++) {
            uint32_t a[MF][4], b[4][2];
#pragma unroll
            for (int mf = 0; mf < MF; mf++) {
                const int r = wm * (MF * 16) + mf * 16 + a_row_l;
                ldsm_x4(a[mf][0], a[mf][1], a[mf][2], a[mf][3],
                        As + r * A_STRIDE_H + ks * 16 + a_col_l);
            }
#pragma unroll
            for (int nfp = 0; nfp < 2; nfp++) {
                const int cn = wn * 32 + nfp * 16 + b_row_l;
                ldsm_x4(b[2 * nfp][0], b[2 * nfp][1], b[2 * nfp + 1][0], b[2 * nfp + 1][1],
                        Bs + cn * A_STRIDE_H + ks * 16 + b_col_l);
            }
#pragma unroll
            for (int mf = 0; mf < MF; mf++)
#pragma unroll
                for (int nf = 0; nf < 4; nf++)
                    asm volatile(
                        "mma.sync.aligned.m16n8k16.row.col.f32.f16.f16.f32 "
                        "{%0,%1,%2,%3}, {%4,%5,%6,%7}, {%8,%9}, {%0,%1,%2,%3};"
                        : "+f"(c[mf][nf][0]), "+f"(c[mf][nf][1]),
                          "+f"(c[mf][nf][2]), "+f"(c[mf][nf][3])
                        : "r"(a[mf][0]), "r"(a[mf][1]), "r"(a[mf][2]), "r"(a[mf][3]),
                          "r"(b[nf][0]), "r"(b[nf][1]));
        }
        slot++; if (slot == 3) slot = 0;
    }

    // ---- epilogue ----
#pragma unroll
    for (int mf = 0; mf < MF; mf++) {
        const int r0 = bm + wm * (MF * 16) + mf * 16 + gid;
#pragma unroll
        for (int nf = 0; nf < 4; nf++) {
            const int cn = bn + wn * 32 + nf * 8 + tig * 2;
#pragma unroll
            for (int half = 0; half < 2; half++) {
                const int row = r0 + half * 8;
                float v0 = c[mf][nf][half * 2 + 0] * alpha;
                float v1 = c[mf][nf][half * 2 + 1] * alpha;
                if (flags & FLAG_BIAS)  { v0 += bias[cn]; v1 += bias[cn + 1]; }
                if (flags & FLAG_RESID) {
                    v0 += resid[(size_t)row * ldr + cn];
                    v1 += resid[(size_t)row * ldr + cn + 1];
                }
                if (flags & FLAG_RELU)  { v0 = fmaxf(v0, 0.f); v1 = fmaxf(v1, 0.f); }
                if (flags & FLAG_OUT16) {
                    *(__half2*)((__half*)C + (size_t)row * ldc + cn) =
                        __floats2half2_rn(v0, v1);
                } else {
                    float* crow = (float*)C + (size_t)row * ldc + cn;
                    crow[0] = v0; crow[1] = v1;
                }
            }
        }
    }
}

__global__ __launch_bounds__(256, 2)
void gemm_h_m128(const __half* __restrict__ A, int lda,
                 const __half* __restrict__ A2, int lda2, int ksplit,
                 const __half* __restrict__ Bm, int ldb,
                 void* __restrict__ C, int ldc,
                 const float* __restrict__ bias,
                 const float* __restrict__ resid, int ldr,
                 int K, float alpha, int flags)
{
    gemm_body<4>(A, lda, A2, lda2, ksplit, Bm, ldb, C, ldc,
                 bias, resid, ldr, K, alpha, flags,
                 blockIdx.y * 128, blockIdx.x * 128);
}

// 3 CTAs/SM: forces <=84 regs; MF=2 needs ~80, no spill expected
__global__ __launch_bounds__(256, 3)
void gemm_h_m64(const __half* __restrict__ A, int lda,
                const __half* __restrict__ A2, int lda2, int ksplit,
                const __half* __restrict__ Bm, int ldb,
                void* __restrict__ C, int ldc,
                const float* __restrict__ bias,
                const float* __restrict__ resid, int ldr,
                int K, float alpha, int flags)
{
    gemm_body<2>(A, lda, A2, lda2, ksplit, Bm, ldb, C, ldc,
                 bias, resid, ldr, K, alpha, flags,
                 blockIdx.y * 64, blockIdx.x * 128);
}

// ---- batched 4x (512x512x256) precompute GEMM -> fp16 out (proven R11) ----
struct GemmEntry { const __half* A; const __half* Bm; __half* C; int ldc; float alpha; };
struct GemmBatch4 { GemmEntry e[4]; };

__global__ __launch_bounds__(256, 2)
void gemm_h_b4(GemmBatch4 p)
{
    const GemmEntry& e = p.e[blockIdx.z];
    gemm_body<4>(e.A, 512, nullptr, 0, 0, e.Bm, 512, e.C, e.ldc,
                 nullptr, nullptr, 0, 256, e.alpha, FLAG_OUT16,
                 blockIdx.y * 128, blockIdx.x * 128);
}

// ---------------- flash attention: 256 threads, CHUNK=16 (proven R11) ------
#define CHUNK 16
#define NCHUNK (N_ / CHUNK)                // 4
#define CHUNK_FLOATS (CHUNK * D_)          // 8192
#define ATTN_SMEM (2 * CHUNK_FLOATS * 4)   // 64 KB

__global__ __launch_bounds__(256)
void attention_kernel(const float* __restrict__ seq,
                      const void* __restrict__ mask,
                      const float* __restrict__ qt,   // [B,1024] fp32
                      __half* __restrict__ ctx,       // [B,1024] fp16
                      float* __restrict__ wout)       // [B,64]
{
    extern __shared__ float s_buf[];       // [2][CHUNK_FLOATS]
    __shared__ float s_all[128];
    __shared__ float s_m[2], s_l[2], s_f[2], s_e[2][CHUNK];
    __shared__ unsigned char s_mask[64];

    const int b = blockIdx.x, tid = threadIdx.x;
    const int warp = tid >> 5, lane = tid & 31;
    const float* sbp = seq + (size_t)b * N_ * D_;

    float4 q0f[4], q1f[4];
    {
        const float4* q0p = (const float4*)(qt + (size_t)b * 1024);
        const float4* q1p = q0p + 128;
#pragma unroll
        for (int i = 0; i < 4; i++) {
            q0f[i] = q0p[lane + 32 * i];
            q1f[i] = q1p[lane + 32 * i];
        }
    }

    auto stage = [&](int c, int buf) {
        float* dst = s_buf + buf * CHUNK_FLOATS;
        const float* src = sbp + c * CHUNK_FLOATS;
#pragma unroll
        for (int i = 0; i < 8; i++) {
            const int e = (tid + 256 * i) * 4;
            cp16(dst + e, src + e);
        }
        asm volatile("cp.async.commit_group;" ::: "memory");
    };

    stage(0, 0);

    if (tid < 64) {
        unsigned int mv;
        if (g_mask_word) mv = ((const unsigned int*)mask)[(size_t)b * N_ + tid];
        else             mv = ((const unsigned char*)mask)[(size_t)b * N_ + tid];
        s_mask[tid] = (mv != 0u) ? 1 : 0;
    }
    if (tid < 2) { s_m[tid] = -3e38f; s_l[tid] = 0.f; }
    __syncthreads();

    float a00 = 0.f, a01 = 0.f, a10 = 0.f, a11 = 0.f;

    for (int c = 0; c < NCHUNK; c++) {
        const int buf = c & 1;
        asm volatile("cp.async.wait_group 0;" ::: "memory");
        __syncthreads();
        if (c < NCHUNK - 1) stage(c + 1, buf ^ 1);

        const float* rows = s_buf + buf * CHUNK_FLOATS;

        // scores: warp w handles chunk rows 2w, 2w+1 (both heads)
#pragma unroll
        for (int rr = 0; rr < 2; rr++) {
            const int k = 2 * warp + rr;
            const float4* r4 = (const float4*)(rows + k * D_);
            float a0 = 0.f, a1 = 0.f;
#pragma unroll
            for (int i = 0; i < 4; i++) {
                float4 s = r4[lane + 32 * i];
                a0 += s.x * q0f[i].x + s.y * q0f[i].y + s.z * q0f[i].z + s.w * q0f[i].w;
                a1 += s.x * q1f[i].x + s.y * q1f[i].y + s.z * q1f[i].z + s.w * q1f[i].w;
            }
#pragma unroll
            for (int o = 16; o; o >>= 1) {
                a0 += __shfl_xor_sync(0xffffffffu, a0, o);
                a1 += __shfl_xor_sync(0xffffffffu, a1, o);
            }
            if (lane == 0) {
                const int kg = c * CHUNK + k;
                const bool mk = s_mask[kg] != 0;
                s_all[kg]      = mk ? -1e10f : a0;
                s_all[64 + kg] = mk ? -1e10f : a1;
            }
        }
        __syncthreads();

        // online softmax update (warp 0 -> head 0, warp 1 -> head 1)
        if (warp < 2) {
            const int h = warp;
            float s = (lane < CHUNK) ? s_all[h * 64 + c * CHUNK + lane] : -3e38f;
            float cm = s;
#pragma unroll
            for (int o = 16; o; o >>= 1) cm = fmaxf(cm, __shfl_xor_sync(0xffffffffu, cm, o));
            const float m_old = s_m[h];
            const float m_new = fmaxf(m_old, cm);
            float e = (lane < CHUNK) ? __expf(s - m_new) : 0.f;
            float se = e;
#pragma unroll
            for (int o = 16; o; o >>= 1) se += __shfl_xor_sync(0xffffffffu, se, o);
            if (lane < CHUNK) s_e[h][lane] = e;
            if (lane == 0) {
                const float f = __expf(m_old - m_new);
                s_f[h] = f; s_m[h] = m_new;
                s_l[h] = s_l[h] * f + se;
            }
        }
        __syncthreads();

        // accumulate: thread owns cols (2*tid, 2*tid+1); no trailing sync
        const float f0 = s_f[0], f1 = s_f[1];
        a00 *= f0; a01 *= f0; a10 *= f1; a11 *= f1;
        const float2* rows2 = (const float2*)rows;
#pragma unroll
        for (int k = 0; k < CHUNK; k++) {
            float2 v = rows2[k * 256 + tid];
            const float e0 = s_e[0][k], e1 = s_e[1][k];
            a00 += e0 * v.x; a01 += e0 * v.y;
            a10 += e1 * v.x; a11 += e1 * v.y;
        }
    }

    const float inv0 = 1.f / s_l[0], inv1 = 1.f / s_l[1];
    __half2* orow = (__half2*)(ctx + (size_t)b * 1024);
    orow[tid]       = __floats2half2_rn(a00 * inv0, a01 * inv0);
    orow[256 + tid] = __floats2half2_rn(a10 * inv1, a11 * inv1);

    if (tid < 64) {
        const float m0 = s_m[0], m1 = s_m[1];
        const float at0 = __expf(s_all[tid]      - m0) * inv0;
        const float at1 = __expf(s_all[64 + tid] - m1) * inv1;
        wout[(size_t)b * 64 + tid] = 0.5f * (at0 + at1);
    }
}

// ---------------- layernorm (fp16 out: GEMM operand) ----------------
__global__ __launch_bounds__(128)
void ln_kernel(const float* __restrict__ x, const float* __restrict__ gam,
               const float* __restrict__ bet, __half* __restrict__ y)
{
    const int b = blockIdx.x, tid = threadIdx.x;
    const float* row = x + (size_t)b * 512;
    float v[4]; float s = 0.f;
#pragma unroll
    for (int j = 0; j < 4; j++) { v[j] = row[tid + 128 * j]; s += v[j]; }
    __shared__ float red[4];
#pragma unroll
    for (int o = 16; o; o >>= 1) s += __shfl_xor_sync(0xffffffffu, s, o);
    if ((tid & 31) == 0) red[tid >> 5] = s;
    __syncthreads();
    s = red[0] + red[1] + red[2] + red[3];
    const float mu = s * (1.f / 512.f);
    float var = 0.f;
#pragma unroll
    for (int j = 0; j < 4; j++) { float d = v[j] - mu; var += d * d; }
    __syncthreads();
#pragma unroll
    for (int o = 16; o; o >>= 1) var += __shfl_xor_sync(0xffffffffu, var, o);
    if ((tid & 31) == 0) red[tid >> 5] = var;
    __syncthreads();
    var = (red[0] + red[1] + red[2] + red[3]) * (1.f / 512.f);
    const float rs = rsqrtf(var + 1e-5f);
#pragma unroll
    for (int j = 0; j < 4; j++) {
        const int c = tid + 128 * j;
        y[(size_t)b * 512 + c] = __float2half_rn(gam[c] * (v[j] - mu) * rs + bet[c]);
    }
}

// ---------------- launch ----------------
extern "C" void kernel_launch(void* const* d_in, const int* in_sizes, int n_in,
                              void* d_out, int out_size)
{
    const float* src  = (const float*)d_in[0];
    const float* seq  = (const float*)d_in[1];
    const void*  mask = d_in[2];
    const float* Wq   = (const float*)d_in[3];
    const float* Wk   = (const float*)d_in[4];
    const float* Wv   = (const float*)d_in[5];
    const float* Wo   = (const float*)d_in[6];
    const float* bo   = (const float*)d_in[7];
    const float* ln_g = (const float*)d_in[8];
    const float* ln_b = (const float*)d_in[9];
    const float* W1   = (const float*)d_in[10];
    const float* b1   = (const float*)d_in[11];
    const float* W2   = (const float*)d_in[12];
    const float* b2   = (const float*)d_in[13];
    float* y    = (float*)d_out;                       // [B, 512]
    float* wout = (float*)d_out + (size_t)B_ * 512;    // [B, 64]

    __half *src_h, *Wq_h, *Wk_h, *Wv_h, *WoT, *W1T, *W2T, *CkT, *CvT, *CTX, *LN, *H1;
    float *QT, *PROJ;
    cudaGetSymbolAddress((void**)&src_h, g_src_h);
    cudaGetSymbolAddress((void**)&Wq_h,  g_Wq_h);
    cudaGetSymbolAddress((void**)&Wk_h,  g_Wk_h);
    cudaGetSymbolAddress((void**)&Wv_h,  g_Wv_h);
    cudaGetSymbolAddress((void**)&WoT,   g_WoT_h);
    cudaGetSymbolAddress((void**)&W1T,   g_W1T_h);
    cudaGetSymbolAddress((void**)&W2T,   g_W2T_h);
    cudaGetSymbolAddress((void**)&CkT,   g_CkT);
    cudaGetSymbolAddress((void**)&CvT,   g_CvT);
    cudaGetSymbolAddress((void**)&QT,    g_QT);
    cudaGetSymbolAddress((void**)&CTX,   g_CTX);
    cudaGetSymbolAddress((void**)&PROJ,  g_PROJ);
    cudaGetSymbolAddress((void**)&LN,    g_LN);
    cudaGetSymbolAddress((void**)&H1,    g_H1);

    cudaFuncSetAttribute(gemm_h_m128,
                         cudaFuncAttributeMaxDynamicSharedMemorySize, GEMM_SMEM_MF(4));
    cudaFuncSetAttribute(gemm_h_m64,
                         cudaFuncAttributeMaxDynamicSharedMemorySize, GEMM_SMEM_MF(2));
    cudaFuncSetAttribute(gemm_h_b4,
                         cudaFuncAttributeMaxDynamicSharedMemorySize, GEMM_SMEM_MF(4));
    cudaFuncSetAttribute(attention_kernel,
                         cudaFuncAttributeMaxDynamicSharedMemorySize, ATTN_SMEM);

    dim3 blk(256);

    // fused pre-pass: mask detect + fp16 copies + transposes, one launch
    PrepassArgs pa;
    pa.c[0] = { (const float4*)src, (__half2*)src_h, B_ * 512 / 4 };
    pa.c[1] = { (const float4*)Wq,  (__half2*)Wq_h,  512 * 512 / 4 };
    pa.c[2] = { (const float4*)Wk,  (__half2*)Wk_h,  512 * 512 / 4 };
    pa.c[3] = { (const float4*)Wv,  (__half2*)Wv_h,  512 * 512 / 4 };
    pa.t[0] = { Wo, WoT, 512, 512 };
    pa.t[1] = { W1, W1T, 1024, 512 };
    pa.t[2] = { W2, W2T, 512, 512 };
    pa.mask = (const unsigned int*)mask;
    prepass_kernel<<<dim3(132, 4, 8), blk>>>(pa);

    // precompute: CkT[h512+d][i] = (1/16) sum_k Wk[d,h256+k] Wq[i,h256+k]
    //             CvT[j][h512+i] =        sum_k WoT[j,h256+k] Wv[i,h256+k]
    GemmBatch4 pb;
    pb.e[0] = { Wk_h,       Wq_h,       CkT,                      512,  1.f / 16.f };
    pb.e[1] = { Wk_h + 256, Wq_h + 256, CkT + (size_t)512 * 512,  512,  1.f / 16.f };
    pb.e[2] = { WoT,        Wv_h,       CvT,                      1024, 1.f };
    pb.e[3] = { WoT + 256,  Wv_h + 256, CvT + 512,                1024, 1.f };
    gemm_h_b4<<<dim3(4, 4, 4), blk, GEMM_SMEM_MF(4)>>>(pb);

    // QT = src_h @ CkT^T (fp32 out)
    gemm_h_m128<<<dim3(8, 32), blk, GEMM_SMEM_MF(4)>>>(src_h, 512, nullptr, 0, 0,
                                    CkT, 512, QT, 1024,
                                    nullptr, nullptr, 0, 512, 1.f, 0);
    // flash attention (CTX fp16 out)
    attention_kernel<<<B_, 256, ATTN_SMEM>>>(seq, mask, QT, CTX, wout);
    // PROJ = CTX @ CvT^T + bo + src (fp32 out)
    gemm_h_m64<<<dim3(4, 64), blk, GEMM_SMEM_MF(2)>>>(CTX, 1024, nullptr, 0, 0,
                                    CvT, 1024, PROJ, 512,
                                    bo, src, 512, 1024, 1.f, FLAG_BIAS | FLAG_RESID);
    // LayerNorm (fp16 out)
    ln_kernel<<<B_, 128>>>(PROJ, ln_g, ln_b, LN);
    // H1 = relu([LN | src_h] @ W1T^T + b1) (fp16 out)
    gemm_h_m64<<<dim3(4, 64), blk, GEMM_SMEM_MF(2)>>>(LN, 512, src_h, 512, 512,
                                    W1T, 1024, H1, 512,
                                    b1, nullptr, 0, 1024, 1.f,
                                    FLAG_BIAS | FLAG_RELU | FLAG_OUT16);
    // y = H1 @ W2T^T + b2 (fp32 out)
    gemm_h_m64<<<dim3(4, 64), blk, GEMM_SMEM_MF(2)>>>(H1, 512, nullptr, 0, 0,
                                    W2T, 512, y, 512,
                                    b2, nullptr, 0, 512, 1.f, FLAG_BIAS);
}